// round 3
// baseline (speedup 1.0000x reference)
#include <cuda_runtime.h>
#include <cuda_bf16.h>
#include <math.h>
#include <mma.h>

using namespace nvcuda;

// Problem constants
#define Bv 4
#define Tv 2048
#define Cv 1024
#define Hv 16
#define HDv 64
#define Mv (Bv * Tv)          // 8192 rows
#define QKV_N (3 * Cv)        // 3072

// Scratch (allocation-free rule: __device__ globals)
__device__ float g_qkv[Mv * QKV_N];   // [B*T, 3C] : q | k | v
__device__ float g_y[Mv * Cv];        // attention output [B*T, C]
__device__ float g_rope[2 * Tv * 32]; // [cos|sin][t][freq], bf16-rounded

// ---------------------------------------------------------------------------
// Rope table: cos/sin(t * 10000^(-i/32)) computed in double (fast-math-proof),
// rounded to fp32 then bf16 (matching reference), stored as fp32.
// ---------------------------------------------------------------------------
__global__ void rope_table_kernel(float* __restrict__ rope)
{
    int idx = blockIdx.x * blockDim.x + threadIdx.x;   // t*32 + i
    if (idx >= Tv * 32) return;
    int t = idx >> 5;
    int i = idx & 31;
    // ln(10000)/32 = 9.210340371976184/32
    double inv_freq_d = exp(-(double)i * (9.210340371976184 / 32.0));
    float  inv_freq   = (float)inv_freq_d;
    float  ang        = (float)t * inv_freq;           // fp32 product like reference
    float  cf = (float)cos((double)ang);
    float  sf = (float)sin((double)ang);
    rope[idx]           = __bfloat162float(__float2bfloat16(cf));
    rope[Tv * 32 + idx] = __bfloat162float(__float2bfloat16(sf));
}

// ---------------------------------------------------------------------------
// GEMM (NT): C[M,N] = A[M,K] * B[N,K]^T, fp32 in/out.
// 3xTF32 emulated-fp32: A = Ah + Al, B = Bh + Bl (tf32 splits);
// acc += Ah*Bh + Ah*Bl + Al*Bh  -> effective input precision ~2^-22.
// BM=128, BN=128, BK=32, 256 threads = 8 warps (4x2), warp tile 32x64.
// ---------------------------------------------------------------------------
__global__ void __launch_bounds__(256) gemm_tf32_nt(
    const float* __restrict__ A, const float* __restrict__ B,
    float* __restrict__ C, int M, int N, int K)
{
    constexpr int BM = 128, BN = 128, BK = 32, LD = 36;  // LD*4B = 144B
    extern __shared__ __align__(16) float smem[];
    float* Ah = smem;                 // BM*LD
    float* Al = Ah + BM * LD;
    float* Bh = Al + BM * LD;
    float* Bl = Bh + BN * LD;

    const int tid = threadIdx.x;
    const int m0 = blockIdx.y * BM;
    const int n0 = blockIdx.x * BN;
    const int w  = tid >> 5;
    const int wm = w >> 1;     // 0..3
    const int wn = w & 1;      // 0..1

    wmma::fragment<wmma::accumulator, 16, 16, 8, float> acc[2][4];
#pragma unroll
    for (int i = 0; i < 2; i++)
#pragma unroll
        for (int j = 0; j < 4; j++)
            wmma::fill_fragment(acc[i][j], 0.0f);

    for (int k0 = 0; k0 < K; k0 += BK) {
        // Global -> shared with hi/lo tf32 split
#pragma unroll
        for (int idx = tid; idx < BM * BK / 4; idx += 256) {
            int r  = idx >> 3;
            int c4 = (idx & 7) * 4;
            float4 v = *(const float4*)&A[(size_t)(m0 + r) * K + k0 + c4];
            float4 h, l;
            h.x = wmma::__float_to_tf32(v.x); l.x = wmma::__float_to_tf32(v.x - h.x);
            h.y = wmma::__float_to_tf32(v.y); l.y = wmma::__float_to_tf32(v.y - h.y);
            h.z = wmma::__float_to_tf32(v.z); l.z = wmma::__float_to_tf32(v.z - h.z);
            h.w = wmma::__float_to_tf32(v.w); l.w = wmma::__float_to_tf32(v.w - h.w);
            *(float4*)&Ah[r * LD + c4] = h;
            *(float4*)&Al[r * LD + c4] = l;
        }
#pragma unroll
        for (int idx = tid; idx < BN * BK / 4; idx += 256) {
            int r  = idx >> 3;
            int c4 = (idx & 7) * 4;
            float4 v = *(const float4*)&B[(size_t)(n0 + r) * K + k0 + c4];
            float4 h, l;
            h.x = wmma::__float_to_tf32(v.x); l.x = wmma::__float_to_tf32(v.x - h.x);
            h.y = wmma::__float_to_tf32(v.y); l.y = wmma::__float_to_tf32(v.y - h.y);
            h.z = wmma::__float_to_tf32(v.z); l.z = wmma::__float_to_tf32(v.z - h.z);
            h.w = wmma::__float_to_tf32(v.w); l.w = wmma::__float_to_tf32(v.w - h.w);
            *(float4*)&Bh[r * LD + c4] = h;
            *(float4*)&Bl[r * LD + c4] = l;
        }
        __syncthreads();

#pragma unroll
        for (int kk = 0; kk < BK; kk += 8) {
            wmma::fragment<wmma::matrix_a, 16, 16, 8, wmma::precision::tf32, wmma::row_major> afh[2], afl[2];
            wmma::fragment<wmma::matrix_b, 16, 16, 8, wmma::precision::tf32, wmma::col_major> bfh[4], bfl[4];
#pragma unroll
            for (int i = 0; i < 2; i++) {
                wmma::load_matrix_sync(afh[i], &Ah[(wm * 32 + i * 16) * LD + kk], LD);
                wmma::load_matrix_sync(afl[i], &Al[(wm * 32 + i * 16) * LD + kk], LD);
            }
#pragma unroll
            for (int j = 0; j < 4; j++) {
                wmma::load_matrix_sync(bfh[j], &Bh[(wn * 64 + j * 16) * LD + kk], LD);
                wmma::load_matrix_sync(bfl[j], &Bl[(wn * 64 + j * 16) * LD + kk], LD);
            }
#pragma unroll
            for (int i = 0; i < 2; i++)
#pragma unroll
                for (int j = 0; j < 4; j++) {
                    wmma::mma_sync(acc[i][j], afh[i], bfl[j], acc[i][j]);
                    wmma::mma_sync(acc[i][j], afl[i], bfh[j], acc[i][j]);
                    wmma::mma_sync(acc[i][j], afh[i], bfh[j], acc[i][j]);
                }
        }
        __syncthreads();
    }

#pragma unroll
    for (int i = 0; i < 2; i++)
#pragma unroll
        for (int j = 0; j < 4; j++)
            wmma::store_matrix_sync(
                C + (size_t)(m0 + wm * 32 + i * 16) * N + n0 + wn * 64 + j * 16,
                acc[i][j], N, wmma::mem_row_major);
}

// ---------------------------------------------------------------------------
// Fused RMSNorm(HD=64) + rotary (reads precomputed bf16-rounded cos/sin).
// One block per (b,t) row; warp w handles head w for both q and k. In-place.
// ---------------------------------------------------------------------------
__global__ void __launch_bounds__(512) norm_rope_kernel(
    float* __restrict__ qkv, const float* __restrict__ rope)
{
    const int bt   = blockIdx.x;
    const int t    = bt & (Tv - 1);
    const int warp = threadIdx.x >> 5;
    const int lane = threadIdx.x & 31;

    float* qp = qkv + (size_t)bt * QKV_N + warp * HDv;
    float c = rope[t * 32 + lane];
    float s = rope[Tv * 32 + t * 32 + lane];

#pragma unroll
    for (int p = 0; p < 2; p++) {   // p=0: q, p=1: k
        float* ptr = qp + p * Cv;
        float x1 = ptr[lane];
        float x2 = ptr[lane + 32];
        float ss = x1 * x1 + x2 * x2;
#pragma unroll
        for (int off = 16; off; off >>= 1)
            ss += __shfl_xor_sync(0xffffffffu, ss, off);
        float r = rsqrtf(ss * (1.0f / 64.0f) + 1.1920929e-07f);
        x1 *= r; x2 *= r;
        ptr[lane]      =  x1 * c + x2 * s;
        ptr[lane + 32] = -x1 * s + x2 * c;
    }
}

// ---------------------------------------------------------------------------
// Flash attention, fp32, causal, online softmax.
// Grid: (T/64, B*H). Block 256 = 16x16 threads; each thread owns a 4x4 S tile
// and a 4(row)x4(col) slice of the 64x64 O accumulator.
// ---------------------------------------------------------------------------
__global__ void __launch_bounds__(256) flash_kernel(
    const float* __restrict__ qkv, float* __restrict__ y)
{
    constexpr int LDS_ = 68;   // 68*4B = 272B rows (16B-aligned), pad vs conflicts
    extern __shared__ float sm[];
    float* Qs = sm;
    float* Ks = Qs + 64 * LDS_;
    float* Vs = Ks + 64 * LDS_;
    float* Ps = Vs + 64 * LDS_;

    const int qt  = blockIdx.x;
    const int bh  = blockIdx.y;
    const int b   = bh / Hv;
    const int h   = bh % Hv;
    const int tid = threadIdx.x;
    const int ty  = tid >> 4;
    const int tx  = tid & 15;

    const size_t rowbase = (size_t)b * Tv;
    const int q0 = qt * 64;

    // Load Q tile once
    for (int idx = tid; idx < 64 * 16; idx += 256) {
        int r  = idx >> 4;
        int c4 = (idx & 15) * 4;
        const float* src = qkv + (rowbase + q0 + r) * (size_t)QKV_N + h * HDv + c4;
        *(float4*)&Qs[r * LDS_ + c4] = *(const float4*)src;
    }

    float m_i[4], l_i[4], o[4][4];
#pragma unroll
    for (int i = 0; i < 4; i++) {
        m_i[i] = -1e30f; l_i[i] = 0.0f;
#pragma unroll
        for (int cc = 0; cc < 4; cc++) o[i][cc] = 0.0f;
    }

    for (int jt = 0; jt <= qt; jt++) {
        __syncthreads();   // prev PV readers done (also covers Q-load on iter 0)
        for (int idx = tid; idx < 64 * 16; idx += 256) {
            int r  = idx >> 4;
            int c4 = (idx & 15) * 4;
            size_t roff = (rowbase + jt * 64 + r) * (size_t)QKV_N + h * HDv + c4;
            *(float4*)&Ks[r * LDS_ + c4] = *(const float4*)(qkv + roff + Cv);
            *(float4*)&Vs[r * LDS_ + c4] = *(const float4*)(qkv + roff + 2 * Cv);
        }
        __syncthreads();

        // S = Q K^T (64x64x64)
        float s[4][4];
#pragma unroll
        for (int i = 0; i < 4; i++)
#pragma unroll
            for (int j = 0; j < 4; j++) s[i][j] = 0.0f;

#pragma unroll
        for (int kd = 0; kd < 64; kd += 4) {
            float4 qv[4], kv[4];
#pragma unroll
            for (int i = 0; i < 4; i++)
                qv[i] = *(const float4*)&Qs[(ty * 4 + i) * LDS_ + kd];
#pragma unroll
            for (int j = 0; j < 4; j++)
                kv[j] = *(const float4*)&Ks[(tx * 4 + j) * LDS_ + kd];
#pragma unroll
            for (int i = 0; i < 4; i++)
#pragma unroll
                for (int j = 0; j < 4; j++)
                    s[i][j] += qv[i].x * kv[j].x + qv[i].y * kv[j].y
                             + qv[i].z * kv[j].z + qv[i].w * kv[j].w;
        }

        const bool diag = (jt == qt);
#pragma unroll
        for (int i = 0; i < 4; i++) {
            const int row = ty * 4 + i;   // local row; diag tile: mask col > row
            float mx = -1e30f;
#pragma unroll
            for (int j = 0; j < 4; j++) {
                s[i][j] *= 0.125f;        // 1/sqrt(64)
                if (diag && (tx * 4 + j > row)) s[i][j] = -1e30f;
                mx = fmaxf(mx, s[i][j]);
            }
#pragma unroll
            for (int off = 8; off; off >>= 1)
                mx = fmaxf(mx, __shfl_xor_sync(0xffffffffu, mx, off));
            float mn   = fmaxf(m_i[i], mx);
            float corr = expf(m_i[i] - mn);
            float pj[4];
            float sum = 0.0f;
#pragma unroll
            for (int j = 0; j < 4; j++) {
                pj[j] = expf(s[i][j] - mn);
                sum += pj[j];
            }
#pragma unroll
            for (int off = 8; off; off >>= 1)
                sum += __shfl_xor_sync(0xffffffffu, sum, off);
            l_i[i] = l_i[i] * corr + sum;
            m_i[i] = mn;
#pragma unroll
            for (int cc = 0; cc < 4; cc++) o[i][cc] *= corr;
            *(float4*)&Ps[(ty * 4 + i) * LDS_ + tx * 4] =
                make_float4(pj[0], pj[1], pj[2], pj[3]);
        }
        __syncthreads();

        // O += P V (64x64x64); this thread owns cols tx*4..tx*4+3
#pragma unroll
        for (int j0 = 0; j0 < 64; j0 += 4) {
            float4 pr[4], vr[4];
#pragma unroll
            for (int i = 0; i < 4; i++)
                pr[i] = *(const float4*)&Ps[(ty * 4 + i) * LDS_ + j0];
#pragma unroll
            for (int jj = 0; jj < 4; jj++)
                vr[jj] = *(const float4*)&Vs[(j0 + jj) * LDS_ + tx * 4];
#pragma unroll
            for (int i = 0; i < 4; i++) {
                o[i][0] += pr[i].x * vr[0].x + pr[i].y * vr[1].x + pr[i].z * vr[2].x + pr[i].w * vr[3].x;
                o[i][1] += pr[i].x * vr[0].y + pr[i].y * vr[1].y + pr[i].z * vr[2].y + pr[i].w * vr[3].y;
                o[i][2] += pr[i].x * vr[0].z + pr[i].y * vr[1].z + pr[i].z * vr[2].z + pr[i].w * vr[3].z;
                o[i][3] += pr[i].x * vr[0].w + pr[i].y * vr[1].w + pr[i].z * vr[2].w + pr[i].w * vr[3].w;
            }
        }
    }

    // Normalize and write out: y[b, q, h*64 + c]
#pragma unroll
    for (int i = 0; i < 4; i++) {
        float inv = 1.0f / l_i[i];
        float4 r4 = make_float4(o[i][0] * inv, o[i][1] * inv, o[i][2] * inv, o[i][3] * inv);
        *(float4*)&y[(rowbase + q0 + ty * 4 + i) * (size_t)Cv + h * HDv + tx * 4] = r4;
    }
}

// ---------------------------------------------------------------------------
// Launcher (graph-capturable: kernel launches + attribute setup only)
// ---------------------------------------------------------------------------
extern "C" void kernel_launch(void* const* d_in, const int* in_sizes, int n_in,
                              void* d_out, int out_size)
{
    const float* x      = (const float*)d_in[0];
    const float* w_attn = (const float*)d_in[1];
    const float* w_proj = (const float*)d_in[2];
    float* out = (float*)d_out;

    float *qkv_p = nullptr, *y_p = nullptr, *rope_p = nullptr;
    cudaGetSymbolAddress((void**)&qkv_p, g_qkv);
    cudaGetSymbolAddress((void**)&y_p, g_y);
    cudaGetSymbolAddress((void**)&rope_p, g_rope);

    const int GEMM_SMEM = 4 * 128 * 36 * (int)sizeof(float);  // 73728 B
    cudaFuncSetAttribute(gemm_tf32_nt, cudaFuncAttributeMaxDynamicSharedMemorySize, GEMM_SMEM);

    // 0) rope table (cheap; overlaps nothing it shouldn't — writes only g_rope)
    rope_table_kernel<<<(Tv * 32 + 255) / 256, 256>>>(rope_p);

    // 1) qkv = x @ w_attn^T   [8192,3072]
    gemm_tf32_nt<<<dim3(QKV_N / 128, Mv / 128), 256, GEMM_SMEM>>>(x, w_attn, qkv_p, Mv, QKV_N, Cv);

    // 2) RMSNorm + RoPE on q,k (in place)
    norm_rope_kernel<<<Mv, 512>>>(qkv_p, rope_p);

    // 3) Causal flash attention -> g_y
    const int FLASH_SMEM = 4 * 64 * 68 * (int)sizeof(float);  // 69632 B
    cudaFuncSetAttribute(flash_kernel, cudaFuncAttributeMaxDynamicSharedMemorySize, FLASH_SMEM);
    flash_kernel<<<dim3(Tv / 64, Bv * Hv), 256, FLASH_SMEM>>>(qkv_p, y_p);

    // 4) out = y @ w_proj^T   [8192,1024]
    gemm_tf32_nt<<<dim3(Cv / 128, Mv / 128), 256, GEMM_SMEM>>>(y_p, w_proj, out, Mv, Cv, Cv);
}